// round 14
// baseline (speedup 1.0000x reference)
#include <cuda_runtime.h>
#include <cuda_bf16.h>
#include <math.h>
#include <stdint.h>

#define N_ROWS 32768
#define DIM    256
#define KCODES 8192
#define NZ     (N_ROWS * DIM)

#define CAP      192
#define MARGIN_F 0.35f

// SMEM: A = 4 k-chunks x (128 rows x 64 dim bf16, 128B rows SW128) = 65536 B
//       B = 3 stages  x (128 codes x 64 dim bf16, 128B rows SW128) = 49152 B
#define SM_A 0
#define SM_B 65536
#define SMEM_TOTAL (65536 + 49152)

__device__ __nv_bfloat16 g_zbf[NZ];
__device__ __nv_bfloat16 g_cbbf[KCODES * DIM];
__device__ float  g_esq[KCODES];
__device__ float  g_bestAppx2[N_ROWS * 2];     // per (row, code-half) local min
__device__ int    g_ccnt[N_ROWS];
__device__ int    g_over[N_ROWS];
__device__ float  g_candD[(size_t)N_ROWS * CAP];
__device__ int    g_candC[(size_t)N_ROWS * CAP];
__device__ int    g_cnt[KCODES];
__device__ double g_sse;

// ---------------------------------------------------------------------------
__device__ __forceinline__ uint32_t smem_u32(const void* p) {
    uint32_t a;
    asm("{ .reg .u64 t; cvta.to.shared.u64 t, %1; cvt.u32.u64 %0, t; }"
        : "=r"(a) : "l"(p));
    return a;
}

#define SW128(x) ((x) ^ (((x) >> 3) & 0x70))

#define CP_ASYNC16(dst, src) \
    asm volatile("cp.async.cg.shared.global [%0], [%1], 16;" \
                 :: "r"((uint32_t)(dst)), "l"(src) : "memory")
#define CP_COMMIT() asm volatile("cp.async.commit_group;" ::: "memory")
#define CP_WAIT(n)  asm volatile("cp.async.wait_group %0;" :: "n"(n) : "memory")

__device__ __forceinline__ void ldsm4(uint32_t* r, uint32_t addr) {
    asm volatile("ldmatrix.sync.aligned.m8n8.x4.shared.b16 {%0,%1,%2,%3}, [%4];"
                 : "=r"(r[0]), "=r"(r[1]), "=r"(r[2]), "=r"(r[3]) : "r"(addr));
}

__device__ __forceinline__ void mma16816(float* d, const uint32_t* a, const uint32_t* b) {
    asm volatile(
        "mma.sync.aligned.m16n8k16.row.col.f32.bf16.bf16.f32 "
        "{%0,%1,%2,%3}, {%4,%5,%6,%7}, {%8,%9}, {%0,%1,%2,%3};"
        : "+f"(d[0]), "+f"(d[1]), "+f"(d[2]), "+f"(d[3])
        : "r"(a[0]), "r"(a[1]), "r"(a[2]), "r"(a[3]), "r"(b[0]), "r"(b[1]));
}

__device__ __forceinline__ void cand_insert(int row, int col, float d) {
    int p = atomicAdd(&g_ccnt[row], 1);
    if (p < CAP) {
        g_candD[(size_t)row * CAP + p] = d;
        g_candC[(size_t)row * CAP + p] = col;
    } else {
        g_over[row] = 1;
    }
}

// ---------------------------------------------------------------------------
__global__ void k_cvt(const float* __restrict__ s, __nv_bfloat16* __restrict__ d, int n8) {
    int t = blockIdx.x * blockDim.x + threadIdx.x;
    if (t < n8) {
        float4 a = ((const float4*)s)[t * 2];
        float4 b = ((const float4*)s)[t * 2 + 1];
        __nv_bfloat162 p0 = __floats2bfloat162_rn(a.x, a.y);
        __nv_bfloat162 p1 = __floats2bfloat162_rn(a.z, a.w);
        __nv_bfloat162 p2 = __floats2bfloat162_rn(b.x, b.y);
        __nv_bfloat162 p3 = __floats2bfloat162_rn(b.z, b.w);
        uint4 o;
        o.x = *(uint32_t*)&p0; o.y = *(uint32_t*)&p1;
        o.z = *(uint32_t*)&p2; o.w = *(uint32_t*)&p3;
        ((uint4*)d)[t] = o;
    }
}

__global__ void k_esq_zero(const float* __restrict__ cb) {
    int c = blockIdx.x * blockDim.x + threadIdx.x;
    if (c < KCODES) {
        const float4* p = (const float4*)(cb + (size_t)c * DIM);
        float s = 0.f;
#pragma unroll 8
        for (int i = 0; i < DIM / 4; ++i) {
            float4 v = p[i];
            s += v.x * v.x + v.y * v.y + v.z * v.z + v.w * v.w;
        }
        g_esq[c] = s;
        g_cnt[c] = 0;
#pragma unroll
        for (int r = 0; r < 4; ++r) {
            g_ccnt[c * 4 + r] = 0;
            g_over[c * 4 + r] = 0;
        }
        if (c == 0) g_sse = 0.0;
    }
}

// ---------------------------------------------------------------------------
// GEMM-argmin: 256 CTAs x 256 thr, warp grid 4(rows)x2(codes), warp tile
// 32x64. 3-stage B pipeline (prefetch distance 2). One commit per iter and
// commit happens AFTER the wait, so the correct bound is wait_group 1:
// at iter i the newest committed group is B(i+1); B(i) (committed at i-2)
// must be complete. (wait_group 2 here was the R12 correctness bug.)
// ---------------------------------------------------------------------------
__global__ void __launch_bounds__(256, 2)
k_gemm() {
    extern __shared__ char smem[];
    const uint32_t sb = smem_u32(smem);
    const int tid  = threadIdx.x;
    const int wid  = tid >> 5;
    const int lane = tid & 31;
    const int g    = lane >> 2;
    const int tg   = lane & 3;
    const int wr   = wid & 3;            // row group 0..3
    const int wc   = wid >> 2;           // code half 0..1
    const int m0   = wr * 32;
    const int n0   = wc * 64;
    const int row0 = blockIdx.x * 128;

    // ---- A prologue: 4 chunks x (128 rows x 64 dims), 128B rows, SW128 ----
#pragma unroll
    for (int t = 0; t < 16; ++t) {
        int idx = tid + t * 256;
        int kb  = idx >> 10;
        int j   = idx & 1023;
        int r   = j >> 3;
        int c8  = j & 7;
        uint32_t off = (uint32_t)r * 128 + c8 * 16;
        CP_ASYNC16(sb + SM_A + kb * 16384 + SW128(off),
                   g_zbf + (size_t)(row0 + r) * DIM + kb * 64 + c8 * 8);
    }
    CP_COMMIT();                          // group: A

    // ---- B stages 0 and 1 --------------------------------------------------
#pragma unroll
    for (int sstg = 0; sstg < 2; ++sstg) {
        const int pcc = sstg >> 2, pkb = sstg & 3;   // iters 0,1
#pragma unroll
        for (int t = 0; t < 4; ++t) {
            int idx = tid + t * 256;
            int n   = idx >> 3;
            int c8  = idx & 7;
            uint32_t off = (uint32_t)n * 128 + c8 * 16;
            CP_ASYNC16(sb + SM_B + sstg * 16384 + SW128(off),
                       g_cbbf + (size_t)(pcc * 128 + n) * DIM + pkb * 64 + c8 * 8);
        }
        CP_COMMIT();                      // groups: B0, B1
    }

    // 4 rows per thread: m0+g, +8, +16, +24
    int rows[4];
    rows[0] = row0 + m0 + g;      rows[1] = rows[0] + 8;
    rows[2] = rows[0] + 16;       rows[3] = rows[0] + 24;
    float best[4], thr[4];
#pragma unroll
    for (int r = 0; r < 4; ++r) { best[r] = INFINITY; thr[r] = INFINITY; }

    float acc[2][8][4];                  // [m16 tile][n8 tile][frag]
    uint32_t Af[2][2][4], Bf[3][4];

    const uint32_t a_b0 = (uint32_t)(m0 + (lane & 15)) * 128 + ((lane >> 4) * 16);
    const uint32_t a_b1 = a_b0 + 16 * 128;
    const uint32_t b_b  = (uint32_t)(n0 + (lane & 7) + ((lane >> 4) & 1) * 8) * 128
                        + (((lane >> 3) & 1) * 16);

    int stg = 0;                         // current B stage = i % 3

    for (int cc = 0; cc < 64; ++cc) {
#pragma unroll
        for (int mt = 0; mt < 2; ++mt)
#pragma unroll
            for (int pn = 0; pn < 8; ++pn)
#pragma unroll
                for (int j = 0; j < 4; ++j) acc[mt][pn][j] = 0.f;

#pragma unroll
        for (int kb = 0; kb < 4; ++kb) {
            const int i = cc * 4 + kb;

            // newest committed group is load(i+1); everything up to load(i)
            // must be complete -> allow only 1 pending group
            CP_WAIT(1);
            __syncthreads();

            const uint32_t abase = sb + SM_A + kb * 16384;
            const uint32_t bbase = sb + SM_B + stg * 16384;

            // ---- early head loads: covered by the prefetch-issue block -----
            ldsm4(Bf[0], bbase + SW128(b_b));                   // t=0 (s0,p0)
            ldsm4(Bf[1], bbase + SW128(b_b + 2048));            // t=1 (s0,p1)
            ldsm4(Af[0][0], abase + SW128(a_b0));
            ldsm4(Af[0][1], abase + SW128(a_b1));

            // ---- prefetch B stage for iter i+2 -----------------------------
            if (i + 2 < 256) {
                const int ci  = i + 2;
                const int pcc = ci >> 2, pkb = ci & 3;
                int wstg = stg + 2; if (wstg >= 3) wstg -= 3;
                const uint32_t bb = sb + SM_B + wstg * 16384;
#pragma unroll
                for (int t = 0; t < 4; ++t) {
                    int idx = tid + t * 256;
                    int n   = idx >> 3;
                    int c8  = idx & 7;
                    uint32_t off = (uint32_t)n * 128 + c8 * 16;
                    CP_ASYNC16(bb + SW128(off),
                               g_cbbf + (size_t)(pcc * 128 + n) * DIM + pkb * 64 + c8 * 8);
                }
            }
            CP_COMMIT();   // one commit per iter keeps group counting uniform

            // ---- mainloop: t = s*4+p; B ring depth 3, prefetch distance 2 --
#pragma unroll
            for (int s = 0; s < 4; ++s) {
                if (s < 3) {
                    ldsm4(Af[(s + 1) & 1][0], abase + SW128(a_b0 + (uint32_t)((s + 1) * 32)));
                    ldsm4(Af[(s + 1) & 1][1], abase + SW128(a_b1 + (uint32_t)((s + 1) * 32)));
                }
#pragma unroll
                for (int p = 0; p < 4; ++p) {
                    const int t = s * 4 + p;
                    if (t + 2 <= 15) {
                        const int tp = t + 2;
                        const int p2 = tp & 3, s2 = tp >> 2;
                        ldsm4(Bf[tp % 3],
                              bbase + SW128(b_b + (uint32_t)(p2 * 2048 + s2 * 32)));
                    }
                    mma16816(acc[0][2 * p],     Af[s & 1][0], Bf[t % 3]);
                    mma16816(acc[0][2 * p + 1], Af[s & 1][0], Bf[t % 3] + 2);
                    mma16816(acc[1][2 * p],     Af[s & 1][1], Bf[t % 3]);
                    mma16816(acc[1][2 * p + 1], Af[s & 1][1], Bf[t % 3] + 2);
                }
            }

            if (++stg == 3) stg = 0;
        }

        // ---- chunk epilogue: quad-shared threshold refresh + inserts -------
#pragma unroll
        for (int r = 0; r < 4; ++r) {
            float b0 = best[r];
            b0 = fminf(b0, __shfl_xor_sync(0xffffffffu, b0, 1));
            b0 = fminf(b0, __shfl_xor_sync(0xffffffffu, b0, 2));
            best[r] = b0;
            thr[r]  = b0 + MARGIN_F;
        }
        const int c0 = cc * 128 + n0;
#pragma unroll
        for (int pn = 0; pn < 8; ++pn) {
            const int colg = c0 + pn * 8 + 2 * tg;
            const float e0 = __ldg(&g_esq[colg]);
            const float e1 = __ldg(&g_esq[colg + 1]);
#pragma unroll
            for (int mt = 0; mt < 2; ++mt) {
                const int r0 = mt * 2;
                float d0 = fmaf(acc[mt][pn][0], -2.f, e0);
                float d1 = fmaf(acc[mt][pn][1], -2.f, e1);
                float d2 = fmaf(acc[mt][pn][2], -2.f, e0);
                float d3 = fmaf(acc[mt][pn][3], -2.f, e1);
                if (d0 < thr[r0])     { cand_insert(rows[r0], colg,     d0); if (d0 < best[r0])     { best[r0] = d0;     thr[r0] = d0 + MARGIN_F; } }
                if (d1 < thr[r0])     { cand_insert(rows[r0], colg + 1, d1); if (d1 < best[r0])     { best[r0] = d1;     thr[r0] = d1 + MARGIN_F; } }
                if (d2 < thr[r0 + 1]) { cand_insert(rows[r0 + 1], colg,     d2); if (d2 < best[r0 + 1]) { best[r0 + 1] = d2; thr[r0 + 1] = d2 + MARGIN_F; } }
                if (d3 < thr[r0 + 1]) { cand_insert(rows[r0 + 1], colg + 1, d3); if (d3 < best[r0 + 1]) { best[r0 + 1] = d3; thr[r0 + 1] = d3 + MARGIN_F; } }
            }
        }
    }

#pragma unroll
    for (int r = 0; r < 4; ++r) {
        float b0 = best[r];
        b0 = fminf(b0, __shfl_xor_sync(0xffffffffu, b0, 1));
        b0 = fminf(b0, __shfl_xor_sync(0xffffffffu, b0, 2));
        if (tg == 0) g_bestAppx2[rows[r] * 2 + wc] = b0;
    }
}

// ---------------------------------------------------------------------------
__device__ __forceinline__ float exact_d(const float* z, const float* cb, int row, int c) {
    const float4* zp = (const float4*)(z + (size_t)row * DIM);
    const float4* ep = (const float4*)(cb + (size_t)c * DIM);
    float s0 = 0.f, s1 = 0.f, s2 = 0.f, s3 = 0.f;
#pragma unroll 16
    for (int q = 0; q < 64; ++q) {
        float4 a = zp[q], b = ep[q];
        s0 = fmaf(a.x, b.x, s0);
        s1 = fmaf(a.y, b.y, s1);
        s2 = fmaf(a.z, b.z, s2);
        s3 = fmaf(a.w, b.w, s3);
    }
    return fmaf(-2.0f, (s0 + s1) + (s2 + s3), __ldg(&g_esq[c]));
}

// ---------------------------------------------------------------------------
__global__ void k_rescore_gather(const float* __restrict__ z,
                                 const float* __restrict__ cb,
                                 float* __restrict__ out) {
    const int gw   = (blockIdx.x * blockDim.x + threadIdx.x) >> 5;
    const int lane = threadIdx.x & 31;
    if (gw >= N_ROWS) return;
    const int row = gw;

    float bd = INFINITY;
    int   bi = 0x7fffffff;
    bool  done = false;

    if (!g_over[row]) {
        const float thr = fminf(g_bestAppx2[row * 2], g_bestAppx2[row * 2 + 1]) + MARGIN_F;
        const int   n   = min(g_ccnt[row], CAP);
        const size_t cbase = (size_t)row * CAP;
        if (n <= 32) {
            float ad = (lane < n) ? g_candD[cbase + lane] : INFINITY;
            int   c  = (lane < n) ? g_candC[cbase + lane] : 0x7fffffff;
            unsigned m = __ballot_sync(0xffffffffu, ad <= thr);
            if (__popc(m) == 1) {
                bi = __shfl_sync(0xffffffffu, c, __ffs(m) - 1);
                done = true;
            } else if (ad <= thr) {
                bd = exact_d(z, cb, row, c);
                bi = c;
            }
        } else {
            for (int k = lane; k < n; k += 32) {
                if (g_candD[cbase + k] <= thr) {
                    int c = g_candC[cbase + k];
                    float d = exact_d(z, cb, row, c);
                    if (d < bd || (d == bd && c < bi)) { bd = d; bi = c; }
                }
            }
        }
    } else {
        for (int c = lane; c < KCODES; c += 32) {
            float d = exact_d(z, cb, row, c);
            if (d < bd || (d == bd && c < bi)) { bd = d; bi = c; }
        }
    }

    if (!done) {
#pragma unroll
        for (int off = 16; off > 0; off >>= 1) {
            float od = __shfl_xor_sync(0xffffffffu, bd, off);
            int   oi = __shfl_xor_sync(0xffffffffu, bi, off);
            if (od < bd || (od == bd && oi < bi)) { bd = od; bi = oi; }
        }
    }
    const int idx = bi;

    const float4* q  = (const float4*)(cb + (size_t)idx * DIM);
    const float4* ze = (const float4*)(z + (size_t)row * DIM);
    float4*       o  = (float4*)(out + (size_t)row * DIM);

    float s = 0.f;
#pragma unroll
    for (int i = 0; i < 2; ++i) {
        int c = lane + i * 32;
        float4 a = ze[c];
        float4 b = q[c];
        float4 r;
        r.x = a.x + (b.x - a.x);
        r.y = a.y + (b.y - a.y);
        r.z = a.z + (b.z - a.z);
        r.w = a.w + (b.w - a.w);
        float dx = a.x - b.x, dy = a.y - b.y, dz = a.z - b.z, dw = a.w - b.w;
        s += dx * dx + dy * dy + dz * dz + dw * dw;
        o[c] = r;
    }
#pragma unroll
    for (int off = 16; off > 0; off >>= 1)
        s += __shfl_down_sync(0xffffffffu, s, off);

    if (lane == 0) {
        atomicAdd(&g_sse, (double)s);
        atomicAdd(&g_cnt[idx], 1);
        out[NZ + row] = (float)idx;
    }
}

__global__ void k_final(float* __restrict__ out) {
    __shared__ float red[256];
    int t = threadIdx.x;
    float h = 0.f;
    for (int c = t; c < KCODES; c += 256) {
        float avg = (float)g_cnt[c] / (float)N_ROWS;
        h += avg * logf(avg + 1e-12f);
    }
    red[t] = h;
    __syncthreads();
    for (int s = 128; s > 0; s >>= 1) {
        if (t < s) red[t] += red[t + s];
        __syncthreads();
    }
    if (t == 0) {
        double mse = g_sse / (double)((size_t)N_ROWS * DIM);
        out[NZ + N_ROWS]     = (float)(1.25 * mse);
        out[NZ + N_ROWS + 1] = expf(-red[0]);
    }
}

// ---------------------------------------------------------------------------
extern "C" void kernel_launch(void* const* d_in, const int* in_sizes, int n_in,
                              void* d_out, int out_size) {
    const float* z  = (const float*)d_in[0];
    const float* cb = (const float*)d_in[1];
    float* out = (float*)d_out;

    __nv_bfloat16 *zbf, *cbbf;
    cudaGetSymbolAddress((void**)&zbf,  g_zbf);
    cudaGetSymbolAddress((void**)&cbbf, g_cbbf);

    cudaFuncSetAttribute(k_gemm, cudaFuncAttributeMaxDynamicSharedMemorySize, SMEM_TOTAL);

    k_cvt<<<NZ / 8 / 256, 256>>>(z, zbf, NZ / 8);                       // 1
    k_cvt<<<KCODES * DIM / 8 / 256, 256>>>(cb, cbbf, KCODES * DIM / 8); // 2
    k_esq_zero<<<KCODES / 256, 256>>>(cb);                              // 3
    k_gemm<<<256, 256, SMEM_TOTAL>>>();                                 // 4 <- ncu slot
    k_rescore_gather<<<4096, 256>>>(z, cb, out);                        // 5
    k_final<<<1, 256>>>(out);                                           // 6
}

// round 15
// speedup vs baseline: 1.0323x; 1.0323x over previous
#include <cuda_runtime.h>
#include <cuda_bf16.h>
#include <math.h>
#include <stdint.h>

#define N_ROWS 32768
#define DIM    256
#define KCODES 8192
#define NZ     (N_ROWS * DIM)

#define CAP      192
#define MARGIN_F 0.35f

// SMEM: A = 4 k-chunks x (128 rows x 64 dim bf16, 128B rows SW128) = 65536 B
//       B = 2 stages  x (128 codes x 64 dim bf16, 128B rows SW128) = 32768 B
#define SM_A 0
#define SM_B 65536
#define SMEM_TOTAL 98304

__device__ __nv_bfloat16 g_cbbf[KCODES * DIM];
__device__ float  g_esq[KCODES];
__device__ float  g_bestAppx2[N_ROWS * 2];     // per (row, code-half) local min
__device__ int    g_ccnt[N_ROWS];
__device__ int    g_over[N_ROWS];
__device__ float  g_candD[(size_t)N_ROWS * CAP];
__device__ int    g_candC[(size_t)N_ROWS * CAP];
__device__ int    g_cnt[KCODES];
__device__ double g_sse;

// ---------------------------------------------------------------------------
__device__ __forceinline__ uint32_t smem_u32(const void* p) {
    uint32_t a;
    asm("{ .reg .u64 t; cvta.to.shared.u64 t, %1; cvt.u32.u64 %0, t; }"
        : "=r"(a) : "l"(p));
    return a;
}

#define SW128(x) ((x) ^ (((x) >> 3) & 0x70))

#define CP_ASYNC16(dst, src) \
    asm volatile("cp.async.cg.shared.global [%0], [%1], 16;" \
                 :: "r"((uint32_t)(dst)), "l"(src) : "memory")
#define CP_COMMIT() asm volatile("cp.async.commit_group;" ::: "memory")
#define CP_WAIT0()  asm volatile("cp.async.wait_group 0;" ::: "memory")

__device__ __forceinline__ void ldsm4(uint32_t* r, uint32_t addr) {
    asm volatile("ldmatrix.sync.aligned.m8n8.x4.shared.b16 {%0,%1,%2,%3}, [%4];"
                 : "=r"(r[0]), "=r"(r[1]), "=r"(r[2]), "=r"(r[3]) : "r"(addr));
}

__device__ __forceinline__ void mma16816(float* d, const uint32_t* a, const uint32_t* b) {
    asm volatile(
        "mma.sync.aligned.m16n8k16.row.col.f32.bf16.bf16.f32 "
        "{%0,%1,%2,%3}, {%4,%5,%6,%7}, {%8,%9}, {%0,%1,%2,%3};"
        : "+f"(d[0]), "+f"(d[1]), "+f"(d[2]), "+f"(d[3])
        : "r"(a[0]), "r"(a[1]), "r"(a[2]), "r"(a[3]), "r"(b[0]), "r"(b[1]));
}

__device__ __forceinline__ void cand_insert(int row, int col, float d) {
    int p = atomicAdd(&g_ccnt[row], 1);
    if (p < CAP) {
        g_candD[(size_t)row * CAP + p] = d;
        g_candC[(size_t)row * CAP + p] = col;
    } else {
        g_over[row] = 1;
    }
}

__device__ __forceinline__ uint32_t pack_bf16x2(float a, float b) {
    __nv_bfloat162 p = __floats2bfloat162_rn(a, b);
    return *(uint32_t*)&p;
}

// ---------------------------------------------------------------------------
// k_prep: codebook convert + esq + all per-replay zeroing. One warp per code.
// ---------------------------------------------------------------------------
__global__ void k_prep(const float* __restrict__ cb) {
    const int gw   = (blockIdx.x * blockDim.x + threadIdx.x) >> 5;
    const int lane = threadIdx.x & 31;
    if (gw >= KCODES) return;
    const int c = gw;

    float4 v0 = ((const float4*)(cb + (size_t)c * DIM))[lane * 2];
    float4 v1 = ((const float4*)(cb + (size_t)c * DIM))[lane * 2 + 1];
    float s = v0.x * v0.x + v0.y * v0.y + v0.z * v0.z + v0.w * v0.w
            + v1.x * v1.x + v1.y * v1.y + v1.z * v1.z + v1.w * v1.w;
#pragma unroll
    for (int o = 16; o > 0; o >>= 1)
        s += __shfl_xor_sync(0xffffffffu, s, o);

    uint4 o;
    o.x = pack_bf16x2(v0.x, v0.y);
    o.y = pack_bf16x2(v0.z, v0.w);
    o.z = pack_bf16x2(v1.x, v1.y);
    o.w = pack_bf16x2(v1.z, v1.w);
    ((uint4*)(g_cbbf + (size_t)c * DIM))[lane] = o;

    if (lane == 0) {
        g_esq[c] = s;
        g_cnt[c] = 0;
#pragma unroll
        for (int r = 0; r < 4; ++r) {
            g_ccnt[c * 4 + r] = 0;
            g_over[c * 4 + r] = 0;
        }
        if (c == 0) g_sse = 0.0;
    }
}

// ---------------------------------------------------------------------------
// GEMM-argmin: 256 CTAs x 256 thr, warp grid 4(rows)x2(codes), warp tile
// 32x64. R11-proven mainloop: 2-stage B (wait 0), depth-3 B fragment ring,
// early head loads. A converted fp32->bf16 in-prologue (no g_zbf round trip).
// ---------------------------------------------------------------------------
__global__ void __launch_bounds__(256, 2)
k_gemm(const float* __restrict__ z) {
    extern __shared__ char smem[];
    const uint32_t sb = smem_u32(smem);
    const int tid  = threadIdx.x;
    const int wid  = tid >> 5;
    const int lane = tid & 31;
    const int g    = lane >> 2;
    const int tg   = lane & 3;
    const int wr   = wid & 3;            // row group 0..3
    const int wc   = wid >> 2;           // code half 0..1
    const int m0   = wr * 32;
    const int n0   = wc * 64;
    const int row0 = blockIdx.x * 128;

    // ---- A prologue: load fp32 z, convert, STS into SW128 bf16 layout -----
    // idx <-> (kb 0..3, r 0..127, c8 0..7): 16B smem chunk = 8 bf16 = 8 fp32
#pragma unroll
    for (int t = 0; t < 16; ++t) {
        int idx = tid + t * 256;             // 0..4095
        int kb  = idx >> 10;
        int j   = idx & 1023;
        int r   = j >> 3;
        int c8  = j & 7;
        const float4* src = (const float4*)(z + (size_t)(row0 + r) * DIM + kb * 64 + c8 * 8);
        float4 a = src[0];
        float4 b = src[1];
        uint4 o;
        o.x = pack_bf16x2(a.x, a.y);
        o.y = pack_bf16x2(a.z, a.w);
        o.z = pack_bf16x2(b.x, b.y);
        o.w = pack_bf16x2(b.z, b.w);
        uint32_t off = (uint32_t)r * 128 + c8 * 16;
        *(uint4*)(smem + SM_A + kb * 16384 + SW128(off)) = o;
    }

    // ---- B stage 0 ---------------------------------------------------------
#pragma unroll
    for (int t = 0; t < 4; ++t) {
        int idx = tid + t * 256;
        int n   = idx >> 3;
        int c8  = idx & 7;
        uint32_t off = (uint32_t)n * 128 + c8 * 16;
        CP_ASYNC16(sb + SM_B + SW128(off),
                   g_cbbf + (size_t)n * DIM + c8 * 8);
    }
    CP_COMMIT();

    // 4 rows per thread: m0+g, +8, +16, +24
    int rows[4];
    rows[0] = row0 + m0 + g;      rows[1] = rows[0] + 8;
    rows[2] = rows[0] + 16;       rows[3] = rows[0] + 24;
    float best[4], thr[4];
#pragma unroll
    for (int r = 0; r < 4; ++r) { best[r] = INFINITY; thr[r] = INFINITY; }

    float acc[2][8][4];                  // [m16 tile][n8 tile][frag]
    uint32_t Af[2][2][4], Bf[3][4];

    const uint32_t a_b0 = (uint32_t)(m0 + (lane & 15)) * 128 + ((lane >> 4) * 16);
    const uint32_t a_b1 = a_b0 + 16 * 128;
    const uint32_t b_b  = (uint32_t)(n0 + (lane & 7) + ((lane >> 4) & 1) * 8) * 128
                        + (((lane >> 3) & 1) * 16);

    for (int cc = 0; cc < 64; ++cc) {
#pragma unroll
        for (int mt = 0; mt < 2; ++mt)
#pragma unroll
            for (int pn = 0; pn < 8; ++pn)
#pragma unroll
                for (int j = 0; j < 4; ++j) acc[mt][pn][j] = 0.f;

#pragma unroll
        for (int kb = 0; kb < 4; ++kb) {
            const int i = cc * 4 + kb;

            CP_WAIT0();
            __syncthreads();

            const uint32_t abase = sb + SM_A + kb * 16384;
            const uint32_t bbase = sb + SM_B + (i & 1) * 16384;

            // ---- early head loads: covered by the prefetch-issue block -----
            ldsm4(Bf[0], bbase + SW128(b_b));                   // t=0 (s0,p0)
            ldsm4(Bf[1], bbase + SW128(b_b + 2048));            // t=1 (s0,p1)
            ldsm4(Af[0][0], abase + SW128(a_b0));
            ldsm4(Af[0][1], abase + SW128(a_b1));

            // ---- prefetch next B stage ------------------------------------
            if (i + 1 < 256) {
                const int ci  = i + 1;
                const int pcc = ci >> 2, pkb = ci & 3;
                const uint32_t bb = sb + SM_B + (ci & 1) * 16384;
#pragma unroll
                for (int t = 0; t < 4; ++t) {
                    int idx = tid + t * 256;
                    int n   = idx >> 3;
                    int c8  = idx & 7;
                    uint32_t off = (uint32_t)n * 128 + c8 * 16;
                    CP_ASYNC16(bb + SW128(off),
                               g_cbbf + (size_t)(pcc * 128 + n) * DIM + pkb * 64 + c8 * 8);
                }
            }
            CP_COMMIT();

            // ---- mainloop: t = s*4+p; B ring depth 3, prefetch distance 2 --
#pragma unroll
            for (int s = 0; s < 4; ++s) {
                if (s < 3) {
                    ldsm4(Af[(s + 1) & 1][0], abase + SW128(a_b0 + (uint32_t)((s + 1) * 32)));
                    ldsm4(Af[(s + 1) & 1][1], abase + SW128(a_b1 + (uint32_t)((s + 1) * 32)));
                }
#pragma unroll
                for (int p = 0; p < 4; ++p) {
                    const int t = s * 4 + p;
                    if (t + 2 <= 15) {
                        const int tp = t + 2;
                        const int p2 = tp & 3, s2 = tp >> 2;
                        ldsm4(Bf[tp % 3],
                              bbase + SW128(b_b + (uint32_t)(p2 * 2048 + s2 * 32)));
                    }
                    mma16816(acc[0][2 * p],     Af[s & 1][0], Bf[t % 3]);
                    mma16816(acc[0][2 * p + 1], Af[s & 1][0], Bf[t % 3] + 2);
                    mma16816(acc[1][2 * p],     Af[s & 1][1], Bf[t % 3]);
                    mma16816(acc[1][2 * p + 1], Af[s & 1][1], Bf[t % 3] + 2);
                }
            }
        }

        // ---- chunk epilogue: quad-shared threshold refresh + inserts -------
#pragma unroll
        for (int r = 0; r < 4; ++r) {
            float b0 = best[r];
            b0 = fminf(b0, __shfl_xor_sync(0xffffffffu, b0, 1));
            b0 = fminf(b0, __shfl_xor_sync(0xffffffffu, b0, 2));
            best[r] = b0;
            thr[r]  = b0 + MARGIN_F;
        }
        const int c0 = cc * 128 + n0;
#pragma unroll
        for (int pn = 0; pn < 8; ++pn) {
            const int colg = c0 + pn * 8 + 2 * tg;
            const float e0 = __ldg(&g_esq[colg]);
            const float e1 = __ldg(&g_esq[colg + 1]);
#pragma unroll
            for (int mt = 0; mt < 2; ++mt) {
                const int r0 = mt * 2;
                float d0 = fmaf(acc[mt][pn][0], -2.f, e0);
                float d1 = fmaf(acc[mt][pn][1], -2.f, e1);
                float d2 = fmaf(acc[mt][pn][2], -2.f, e0);
                float d3 = fmaf(acc[mt][pn][3], -2.f, e1);
                if (d0 < thr[r0])     { cand_insert(rows[r0], colg,     d0); if (d0 < best[r0])     { best[r0] = d0;     thr[r0] = d0 + MARGIN_F; } }
                if (d1 < thr[r0])     { cand_insert(rows[r0], colg + 1, d1); if (d1 < best[r0])     { best[r0] = d1;     thr[r0] = d1 + MARGIN_F; } }
                if (d2 < thr[r0 + 1]) { cand_insert(rows[r0 + 1], colg,     d2); if (d2 < best[r0 + 1]) { best[r0 + 1] = d2; thr[r0 + 1] = d2 + MARGIN_F; } }
                if (d3 < thr[r0 + 1]) { cand_insert(rows[r0 + 1], colg + 1, d3); if (d3 < best[r0 + 1]) { best[r0 + 1] = d3; thr[r0 + 1] = d3 + MARGIN_F; } }
            }
        }
    }

#pragma unroll
    for (int r = 0; r < 4; ++r) {
        float b0 = best[r];
        b0 = fminf(b0, __shfl_xor_sync(0xffffffffu, b0, 1));
        b0 = fminf(b0, __shfl_xor_sync(0xffffffffu, b0, 2));
        if (tg == 0) g_bestAppx2[rows[r] * 2 + wc] = b0;
    }
}

// ---------------------------------------------------------------------------
__device__ __forceinline__ float exact_d(const float* z, const float* cb, int row, int c) {
    const float4* zp = (const float4*)(z + (size_t)row * DIM);
    const float4* ep = (const float4*)(cb + (size_t)c * DIM);
    float s0 = 0.f, s1 = 0.f, s2 = 0.f, s3 = 0.f;
#pragma unroll 16
    for (int q = 0; q < 64; ++q) {
        float4 a = zp[q], b = ep[q];
        s0 = fmaf(a.x, b.x, s0);
        s1 = fmaf(a.y, b.y, s1);
        s2 = fmaf(a.z, b.z, s2);
        s3 = fmaf(a.w, b.w, s3);
    }
    return fmaf(-2.0f, (s0 + s1) + (s2 + s3), __ldg(&g_esq[c]));
}

// ---------------------------------------------------------------------------
__global__ void k_rescore_gather(const float* __restrict__ z,
                                 const float* __restrict__ cb,
                                 float* __restrict__ out) {
    const int gw   = (blockIdx.x * blockDim.x + threadIdx.x) >> 5;
    const int lane = threadIdx.x & 31;
    if (gw >= N_ROWS) return;
    const int row = gw;

    float bd = INFINITY;
    int   bi = 0x7fffffff;
    bool  done = false;

    if (!g_over[row]) {
        const float thr = fminf(g_bestAppx2[row * 2], g_bestAppx2[row * 2 + 1]) + MARGIN_F;
        const int   n   = min(g_ccnt[row], CAP);
        const size_t cbase = (size_t)row * CAP;
        if (n <= 32) {
            float ad = (lane < n) ? g_candD[cbase + lane] : INFINITY;
            int   c  = (lane < n) ? g_candC[cbase + lane] : 0x7fffffff;
            unsigned m = __ballot_sync(0xffffffffu, ad <= thr);
            if (__popc(m) == 1) {
                bi = __shfl_sync(0xffffffffu, c, __ffs(m) - 1);
                done = true;
            } else if (ad <= thr) {
                bd = exact_d(z, cb, row, c);
                bi = c;
            }
        } else {
            for (int k = lane; k < n; k += 32) {
                if (g_candD[cbase + k] <= thr) {
                    int c = g_candC[cbase + k];
                    float d = exact_d(z, cb, row, c);
                    if (d < bd || (d == bd && c < bi)) { bd = d; bi = c; }
                }
            }
        }
    } else {
        for (int c = lane; c < KCODES; c += 32) {
            float d = exact_d(z, cb, row, c);
            if (d < bd || (d == bd && c < bi)) { bd = d; bi = c; }
        }
    }

    if (!done) {
#pragma unroll
        for (int off = 16; off > 0; off >>= 1) {
            float od = __shfl_xor_sync(0xffffffffu, bd, off);
            int   oi = __shfl_xor_sync(0xffffffffu, bi, off);
            if (od < bd || (od == bd && oi < bi)) { bd = od; bi = oi; }
        }
    }
    const int idx = bi;

    const float4* q  = (const float4*)(cb + (size_t)idx * DIM);
    const float4* ze = (const float4*)(z + (size_t)row * DIM);
    float4*       o  = (float4*)(out + (size_t)row * DIM);

    float s = 0.f;
#pragma unroll
    for (int i = 0; i < 2; ++i) {
        int c = lane + i * 32;
        float4 a = ze[c];
        float4 b = q[c];
        float4 r;
        r.x = a.x + (b.x - a.x);
        r.y = a.y + (b.y - a.y);
        r.z = a.z + (b.z - a.z);
        r.w = a.w + (b.w - a.w);
        float dx = a.x - b.x, dy = a.y - b.y, dz = a.z - b.z, dw = a.w - b.w;
        s += dx * dx + dy * dy + dz * dz + dw * dw;
        o[c] = r;
    }
#pragma unroll
    for (int off = 16; off > 0; off >>= 1)
        s += __shfl_down_sync(0xffffffffu, s, off);

    if (lane == 0) {
        atomicAdd(&g_sse, (double)s);
        atomicAdd(&g_cnt[idx], 1);
        out[NZ + row] = (float)idx;
    }
}

__global__ void k_final(float* __restrict__ out) {
    __shared__ float red[256];
    int t = threadIdx.x;
    float h = 0.f;
    for (int c = t; c < KCODES; c += 256) {
        float avg = (float)g_cnt[c] / (float)N_ROWS;
        h += avg * logf(avg + 1e-12f);
    }
    red[t] = h;
    __syncthreads();
    for (int s = 128; s > 0; s >>= 1) {
        if (t < s) red[t] += red[t + s];
        __syncthreads();
    }
    if (t == 0) {
        double mse = g_sse / (double)((size_t)N_ROWS * DIM);
        out[NZ + N_ROWS]     = (float)(1.25 * mse);
        out[NZ + N_ROWS + 1] = expf(-red[0]);
    }
}

// ---------------------------------------------------------------------------
extern "C" void kernel_launch(void* const* d_in, const int* in_sizes, int n_in,
                              void* d_out, int out_size) {
    const float* z  = (const float*)d_in[0];
    const float* cb = (const float*)d_in[1];
    float* out = (float*)d_out;

    cudaFuncSetAttribute(k_gemm, cudaFuncAttributeMaxDynamicSharedMemorySize, SMEM_TOTAL);

    k_prep<<<KCODES * 32 / 256, 256>>>(cb);          // 1: cb cvt + esq + zero
    k_gemm<<<256, 256, SMEM_TOTAL>>>(z);             // 2
    k_rescore_gather<<<4096, 256>>>(z, cb, out);     // 3
    k_final<<<1, 256>>>(out);                        // 4
}